// round 4
// baseline (speedup 1.0000x reference)
#include <cuda_runtime.h>

// Rotation_11364483465564 — diagonal phase rotation.
//
// a^T a = diag(0..D-1)  =>  M = expm(i*pi*angle*a^T a) is diagonal,
// M[n] = exp(i*theta*n), theta = fl32(pi_f32 * angle).  kron(M, I2) applies
// phase n to rows 2n and 2n+1 of the (2D, B) complex state.
//
// R3 change: vary the WRITE PATH — the only subsystem untouched so far.
// R0/R1/R2 proved duration invariant under instruction count (6x),
// occupancy (3.7x) and per-thread MLP (4x); DRAM counters show ~8MB/replay
// of DRAM traffic ~= the store volume (reads are L2-resident under graph
// replay). So: keep the cheapest body (R2 smem phase table) and issue the
// output stores as st.global.cs (streaming / evict-first), inputs via
// ld.global.nc.
//
// Precision: arg = fl32(fl32(pi_f32*angle) * n), bit-identical to the
// reference's expm input rounding; accurate sincosf (NOT __sincosf).

#ifndef ROT_D
#define ROT_D 2048
#endif
#ifndef ROT_B
#define ROT_B 256
#endif

static constexpr int PLANE_FLOATS = 2 * ROT_D * ROT_B;   // 1,048,576
static constexpr int PLANE_VEC4   = PLANE_FLOATS / 4;    // 262,144

__device__ __forceinline__ void stcs_f4(float4* p, float4 v) {
    asm volatile("st.global.cs.v4.f32 [%0], {%1, %2, %3, %4};"
                 :: "l"(p), "f"(v.x), "f"(v.y), "f"(v.z), "f"(v.w)
                 : "memory");
}

__global__ __launch_bounds__(256)
void rotation_phase_kernel(const float* __restrict__ angle,
                           const float* __restrict__ xr,
                           const float* __restrict__ xi,
                           float* __restrict__ out)
{
    __shared__ float2 cs[2];   // (cos, sin) for the block's two n values

    const int tid = threadIdx.x;

    if (tid < 2) {
        // theta = fl32(pi_f32 * angle) — identical rounding to reference.
        const float theta = 3.14159265358979323846f * __ldg(angle);
        const int n = 2 * blockIdx.x + tid;
        float s, c;
        sincosf(theta * (float)n, &s, &c);   // fl32(theta*n) matches ref arg
        cs[tid] = make_float2(c, s);
    }

    // Inputs don't depend on the table: issue loads before the barrier.
    const int gid = blockIdx.x * 256 + tid;      // vec4 index in plane
    const float4 r4 = __ldg(reinterpret_cast<const float4*>(xr) + gid);
    const float4 i4 = __ldg(reinterpret_cast<const float4*>(xi) + gid);

    __syncthreads();

    const float2 p = cs[tid >> 7];   // vec4 128..255 -> second n
    const float c = p.x, s = p.y;

    float4 o_re, o_im;
    o_re.x = fmaf(c, r4.x, -s * i4.x);
    o_re.y = fmaf(c, r4.y, -s * i4.y);
    o_re.z = fmaf(c, r4.z, -s * i4.z);
    o_re.w = fmaf(c, r4.w, -s * i4.w);
    o_im.x = fmaf(s, r4.x,  c * i4.x);
    o_im.y = fmaf(s, r4.y,  c * i4.y);
    o_im.z = fmaf(s, r4.z,  c * i4.z);
    o_im.w = fmaf(s, r4.w,  c * i4.w);

    float4* out4 = reinterpret_cast<float4*>(out);
    stcs_f4(out4 + gid,              o_re);
    stcs_f4(out4 + gid + PLANE_VEC4, o_im);
}

extern "C" void kernel_launch(void* const* d_in, const int* in_sizes, int n_in,
                              void* d_out, int out_size)
{
    (void)in_sizes; (void)n_in; (void)out_size;
    const float* angle = (const float*)d_in[0];
    // d_in[1] ('a' matrix) unused: a^T a = diag(0..D-1) analytically.
    const float* xr = (const float*)d_in[2];
    const float* xi = (const float*)d_in[3];
    float* out = (float*)d_out;

    rotation_phase_kernel<<<PLANE_VEC4 / 256, 256>>>(angle, xr, xi, out);
}

// round 5
// speedup vs baseline: 1.0431x; 1.0431x over previous
#include <cuda_runtime.h>

// Rotation_11364483465564 — diagonal phase rotation.
//
// a^T a = diag(0..D-1)  =>  M = expm(i*pi*angle*a^T a) is diagonal,
// M[n] = exp(i*theta*n), theta = fl32(pi_f32 * angle).  kron(M, I2) applies
// phase n to rows 2n and 2n+1 of the (2D, B) complex state.
//
// R4: launch-envelope minimization. Evidence from R0-R3: duration invariant
// under instruction count (6x), occupancy (18-75%), MLP (2-8), write policy,
// and even cold-vs-warm L2 — every utilization <= 16%. T_chip decomposition
// says fixed launch overhead (~5000 cyc) dominates a ~1.5-2us memory phase.
// This round tunes the only remaining knob: one balanced wave of 256 CTAs x
// 512 threads (best observed grid regime), smem phase table, 4 front-batched
// LDG.128 per thread.
//
// Precision: arg = fl32(fl32(pi_f32*angle) * n), bit-identical to the
// reference's expm input rounding; accurate sincosf (NOT __sincosf).

#ifndef ROT_D
#define ROT_D 2048
#endif
#ifndef ROT_B
#define ROT_B 256
#endif

static constexpr int PLANE_FLOATS = 2 * ROT_D * ROT_B;   // 1,048,576
static constexpr int PLANE_VEC4   = PLANE_FLOATS / 4;    // 262,144
// 256 blocks x 512 threads; each block owns 1024 consecutive vec4
// = 16 rows = 8 Fock indices n. Each thread: 2 vec4 per plane.

__global__ __launch_bounds__(512)
void rotation_phase_kernel(const float* __restrict__ angle,
                           const float* __restrict__ xr,
                           const float* __restrict__ xi,
                           float* __restrict__ out)
{
    __shared__ float2 cs[8];   // (cos, sin) for the block's 8 n values

    const int tid = threadIdx.x;

    if (tid < 8) {
        // theta = fl32(pi_f32 * angle) — identical rounding to reference.
        const float theta = 3.14159265358979323846f * __ldg(angle);
        const int n = 8 * blockIdx.x + tid;
        float s, c;
        sincosf(theta * (float)n, &s, &c);   // fl32(theta*n) matches ref arg
        cs[tid] = make_float2(c, s);
    }

    // Two vec4 per plane per thread; front-batch all 4 loads (MLP=4),
    // issued BEFORE the barrier (independent of the table).
    const int g0 = blockIdx.x * 1024 + tid;         // chunk 0
    const int g1 = g0 + 512;                        // chunk 1
    const float4* __restrict__ xr4 = reinterpret_cast<const float4*>(xr);
    const float4* __restrict__ xi4 = reinterpret_cast<const float4*>(xi);

    const float4 r0 = __ldg(xr4 + g0);
    const float4 r1 = __ldg(xr4 + g1);
    const float4 i0 = __ldg(xi4 + g0);
    const float4 i1 = __ldg(xi4 + g1);

    __syncthreads();

    // local n = (offset within block's 1024 vec4) >> 7
    const float2 p0 = cs[tid >> 7];           // 0..3
    const float2 p1 = cs[(512 + tid) >> 7];   // 4..7

    float4* out4 = reinterpret_cast<float4*>(out);

    float4 o;
    o.x = fmaf(p0.x, r0.x, -p0.y * i0.x);
    o.y = fmaf(p0.x, r0.y, -p0.y * i0.y);
    o.z = fmaf(p0.x, r0.z, -p0.y * i0.z);
    o.w = fmaf(p0.x, r0.w, -p0.y * i0.w);
    out4[g0] = o;
    o.x = fmaf(p0.y, r0.x,  p0.x * i0.x);
    o.y = fmaf(p0.y, r0.y,  p0.x * i0.y);
    o.z = fmaf(p0.y, r0.z,  p0.x * i0.z);
    o.w = fmaf(p0.y, r0.w,  p0.x * i0.w);
    out4[g0 + PLANE_VEC4] = o;

    o.x = fmaf(p1.x, r1.x, -p1.y * i1.x);
    o.y = fmaf(p1.x, r1.y, -p1.y * i1.y);
    o.z = fmaf(p1.x, r1.z, -p1.y * i1.z);
    o.w = fmaf(p1.x, r1.w, -p1.y * i1.w);
    out4[g1] = o;
    o.x = fmaf(p1.y, r1.x,  p1.x * i1.x);
    o.y = fmaf(p1.y, r1.y,  p1.x * i1.y);
    o.z = fmaf(p1.y, r1.z,  p1.x * i1.z);
    o.w = fmaf(p1.y, r1.w,  p1.x * i1.w);
    out4[g1 + PLANE_VEC4] = o;
}

extern "C" void kernel_launch(void* const* d_in, const int* in_sizes, int n_in,
                              void* d_out, int out_size)
{
    (void)in_sizes; (void)n_in; (void)out_size;
    const float* angle = (const float*)d_in[0];
    // d_in[1] ('a' matrix) unused: a^T a = diag(0..D-1) analytically.
    const float* xr = (const float*)d_in[2];
    const float* xi = (const float*)d_in[3];
    float* out = (float*)d_out;

    rotation_phase_kernel<<<256, 512>>>(angle, xr, xi, out);
}

// round 6
// speedup vs baseline: 1.0739x; 1.0296x over previous
#include <cuda_runtime.h>

// Rotation_11364483465564 — diagonal phase rotation.
//
// a^T a = diag(0..D-1)  =>  M = expm(i*pi*angle*a^T a) is diagonal,
// M[n] = exp(i*theta*n), theta = fl32(pi_f32 * angle).  kron(M, I2) applies
// phase n to rows 2n and 2n+1 of the (2D, B) complex state.
//
// R5 (final): barrier-free variant of the best-measured config (R4:
// 256 CTAs x 512 threads, one balanced wave, 4 front-batched LDG.128/thread).
// n is warp-uniform per chunk in this layout (n0 = g0>>7, n1 = n0+4), so the
// phase pair is computed with ONE warp-paced sincosf (lane parity selects
// n0 vs n1) and broadcast with SHFL — no smem table, no __syncthreads.
// The sincos executes entirely under the shadow of the in-flight loads.
//
// Evidence R0-R5: duration invariant under instruction count (6x), occupancy
// (18-75%), MLP (2-8), write policy, grid shape — every utilization <=16%.
// The kernel is launch-envelope-bound (T_ovh ~5000 cyc) at this 16MB size;
// this version minimizes the residual body/structural cost.
//
// Precision: arg = fl32(fl32(pi_f32*angle) * n) — bit-identical to the
// reference's expm-input rounding ((float)n exact for n < 2048); accurate
// sincosf (NOT __sincosf — too lossy at |arg| ~ 2e4).

#ifndef ROT_D
#define ROT_D 2048
#endif
#ifndef ROT_B
#define ROT_B 256
#endif

static constexpr int PLANE_FLOATS = 2 * ROT_D * ROT_B;   // 1,048,576
static constexpr int PLANE_VEC4   = PLANE_FLOATS / 4;    // 262,144
// 256 blocks x 512 threads; block owns 1024 consecutive vec4 = 8 n-values.
// Thread handles vec4 {g0, g0+512} in each plane; n0 = g0>>7, n1 = n0+4.

__global__ __launch_bounds__(512)
void rotation_phase_kernel(const float* __restrict__ angle,
                           const float* __restrict__ xr,
                           const float* __restrict__ xi,
                           float* __restrict__ out)
{
    const int tid  = threadIdx.x;
    const int lane = tid & 31;

    // Front-batch all 4 loads (MLP=4) before any math.
    const int g0 = blockIdx.x * 1024 + tid;
    const int g1 = g0 + 512;
    const float4* __restrict__ xr4 = reinterpret_cast<const float4*>(xr);
    const float4* __restrict__ xi4 = reinterpret_cast<const float4*>(xi);

    const float4 r0 = __ldg(xr4 + g0);
    const float4 r1 = __ldg(xr4 + g1);
    const float4 i0 = __ldg(xi4 + g0);
    const float4 i1 = __ldg(xi4 + g1);

    // theta = fl32(pi_f32 * angle) — identical rounding to reference.
    const float theta = 3.14159265358979323846f * __ldg(angle);

    // Warp-uniform Fock indices for this thread's two chunks.
    // n0 = g0 >> 7 (uniform across the warp's 32 consecutive tids),
    // n1 = n0 + 4.  Even lanes evaluate n0, odd lanes n1 (one warp-paced
    // sincosf total), then broadcast both pairs via shfl.
    const int n0 = (blockIdx.x * 1024 + (tid & ~31)) >> 7;
    const float n_mine = (float)(n0 + ((lane & 1) << 2));

    float s, c;
    sincosf(theta * n_mine, &s, &c);     // fl32(theta*n) matches ref arg

    const unsigned FULL = 0xFFFFFFFFu;
    const float c0 = __shfl_sync(FULL, c, 0);
    const float s0 = __shfl_sync(FULL, s, 0);
    const float c1 = __shfl_sync(FULL, c, 1);
    const float s1 = __shfl_sync(FULL, s, 1);

    float4* out4 = reinterpret_cast<float4*>(out);

    float4 o;
    o.x = fmaf(c0, r0.x, -s0 * i0.x);
    o.y = fmaf(c0, r0.y, -s0 * i0.y);
    o.z = fmaf(c0, r0.z, -s0 * i0.z);
    o.w = fmaf(c0, r0.w, -s0 * i0.w);
    out4[g0] = o;
    o.x = fmaf(s0, r0.x,  c0 * i0.x);
    o.y = fmaf(s0, r0.y,  c0 * i0.y);
    o.z = fmaf(s0, r0.z,  c0 * i0.z);
    o.w = fmaf(s0, r0.w,  c0 * i0.w);
    out4[g0 + PLANE_VEC4] = o;

    o.x = fmaf(c1, r1.x, -s1 * i1.x);
    o.y = fmaf(c1, r1.y, -s1 * i1.y);
    o.z = fmaf(c1, r1.z, -s1 * i1.z);
    o.w = fmaf(c1, r1.w, -s1 * i1.w);
    out4[g1] = o;
    o.x = fmaf(s1, r1.x,  c1 * i1.x);
    o.y = fmaf(s1, r1.y,  c1 * i1.y);
    o.z = fmaf(s1, r1.z,  c1 * i1.z);
    o.w = fmaf(s1, r1.w,  c1 * i1.w);
    out4[g1 + PLANE_VEC4] = o;
}

extern "C" void kernel_launch(void* const* d_in, const int* in_sizes, int n_in,
                              void* d_out, int out_size)
{
    (void)in_sizes; (void)n_in; (void)out_size;
    const float* angle = (const float*)d_in[0];
    // d_in[1] ('a' matrix) unused: a^T a = diag(0..D-1) analytically.
    const float* xr = (const float*)d_in[2];
    const float* xi = (const float*)d_in[3];
    float* out = (float*)d_out;

    rotation_phase_kernel<<<256, 512>>>(angle, xr, xi, out);
}